// round 1
// baseline (speedup 1.0000x reference)
#include <cuda_runtime.h>
#include <math.h>

// ---------------- problem constants ----------------
#define BB   2
#define N1L  2048
#define N2L  128
#define TT   2176          // N1 + N2
#define DD   1024
#define HH   16
#define DHH  64
#define ND3  3072          // 3*D
#define NVTILES 32         // video q/k tiles of 64 rows (2048/64)
#define NKT  34            // T/64

// ---------------- scratch (__device__ globals; no allocs allowed) ----------------
__device__ float g_qkv[BB * TT * ND3];        // [B, T, 3*D]  (qkv1 rows 0..2047, qkv2 rows 2048..2175 per b)
__device__ float g_q[BB * HH * TT * DHH];     // [B,H,T,64]  (scale 1/8 folded in)
__device__ float g_k[BB * HH * TT * DHH];
__device__ float g_v[BB * HH * TT * DHH];
__device__ float g_x[BB * TT * DD];           // attention output, heads merged

// =====================================================================
// Generic tiled SGEMM: C[remap_c(r)] = A[remap_a(r)] @ W + bias
// Tiles: BM=128, BN=128, BK=8; 256 threads; 8x8 per thread.
// remap(r) = (r / per) * span + base + (r % per)
// =====================================================================
__global__ __launch_bounds__(256) void sgemm_kernel(
    const float* __restrict__ A, const float* __restrict__ W,
    const float* __restrict__ bias, float* __restrict__ C,
    int M, int N, int K,
    int a_per, int a_base, int a_span,
    int c_per, int c_base, int c_span)
{
    __shared__ float As[8][132];   // transposed: As[k][m], padded
    __shared__ float Bs[8][128];   // Bs[k][n]

    int tid = threadIdx.x;
    int bm = blockIdx.y, bn = blockIdx.x;
    int tx = tid & 15, ty = tid >> 4;

    // A load mapping: thread -> (row 0..127, k-quad 0 or 4)
    int a_row = tid >> 1;
    int a_kq  = (tid & 1) * 4;
    int gm_a  = bm * 128 + a_row;
    const float* a_ptr = A + ((gm_a / a_per) * a_span + a_base + (gm_a % a_per)) * K + a_kq;

    // W load mapping: thread -> (k-row 0..7, 4 cols)
    int b_kr = tid >> 5;
    int b_nq = (tid & 31) * 4;
    const float* w_ptr = W + b_kr * N + bn * 128 + b_nq;

    float acc[8][8];
#pragma unroll
    for (int i = 0; i < 8; i++)
#pragma unroll
        for (int j = 0; j < 8; j++) acc[i][j] = 0.f;

    for (int kk = 0; kk < K; kk += 8) {
        float4 av = *(const float4*)(a_ptr + kk);
        float4 bv = *(const float4*)(w_ptr + kk * N);
        __syncthreads();
        As[a_kq + 0][a_row] = av.x;
        As[a_kq + 1][a_row] = av.y;
        As[a_kq + 2][a_row] = av.z;
        As[a_kq + 3][a_row] = av.w;
        *(float4*)&Bs[b_kr][b_nq] = bv;
        __syncthreads();
#pragma unroll
        for (int k = 0; k < 8; k++) {
            float4 a0 = *(const float4*)&As[k][ty * 8];
            float4 a1 = *(const float4*)&As[k][ty * 8 + 4];
            float4 b0 = *(const float4*)&Bs[k][tx * 8];
            float4 b1 = *(const float4*)&Bs[k][tx * 8 + 4];
            float ar[8] = {a0.x, a0.y, a0.z, a0.w, a1.x, a1.y, a1.z, a1.w};
            float br[8] = {b0.x, b0.y, b0.z, b0.w, b1.x, b1.y, b1.z, b1.w};
#pragma unroll
            for (int i = 0; i < 8; i++)
#pragma unroll
                for (int j = 0; j < 8; j++) acc[i][j] += ar[i] * br[j];
        }
    }

    int cn = bn * 128 + tx * 8;
    float4 bi0 = *(const float4*)(bias + cn);
    float4 bi1 = *(const float4*)(bias + cn + 4);
    float bb[8] = {bi0.x, bi0.y, bi0.z, bi0.w, bi1.x, bi1.y, bi1.z, bi1.w};
#pragma unroll
    for (int i = 0; i < 8; i++) {
        int gm = bm * 128 + ty * 8 + i;
        int crow = (gm / c_per) * c_span + c_base + (gm % c_per);
        float4 o0 = make_float4(acc[i][0] + bb[0], acc[i][1] + bb[1], acc[i][2] + bb[2], acc[i][3] + bb[3]);
        float4 o1 = make_float4(acc[i][4] + bb[4], acc[i][5] + bb[5], acc[i][6] + bb[6], acc[i][7] + bb[7]);
        *(float4*)(C + crow * N + cn)     = o0;
        *(float4*)(C + crow * N + cn + 4) = o1;
    }
}

// =====================================================================
// RMSNorm(q,k) + scatter q/k/v from [B,T,3D] into [B,H,T,64].
// One warp per (b,t,h). Scale 1/8 folded into q.
// =====================================================================
__global__ __launch_bounds__(256) void rms_scatter_kernel(
    const float* __restrict__ gq1, const float* __restrict__ gk1,
    const float* __restrict__ gq2, const float* __restrict__ gk2)
{
    int warp = (blockIdx.x * blockDim.x + threadIdx.x) >> 5;
    int lane = threadIdx.x & 31;
    if (warp >= BB * TT * HH) return;
    int h = warp % HH;
    int bt = warp / HH;
    int t = bt % TT;
    int b = bt / TT;

    const float* base = g_qkv + (b * TT + t) * ND3;
    const float* gq = (t < N1L) ? gq1 : gq2;
    const float* gk = (t < N1L) ? gk1 : gk2;

    int d0 = lane * 2;
    float2 qv = *(const float2*)(base + h * DHH + d0);
    float2 kv = *(const float2*)(base + DD + h * DHH + d0);
    float2 vv = *(const float2*)(base + 2 * DD + h * DHH + d0);

    float ssq = qv.x * qv.x + qv.y * qv.y;
    float ssk = kv.x * kv.x + kv.y * kv.y;
#pragma unroll
    for (int off = 16; off > 0; off >>= 1) {
        ssq += __shfl_xor_sync(0xffffffffu, ssq, off);
        ssk += __shfl_xor_sync(0xffffffffu, ssk, off);
    }
    float rq = rsqrtf(ssq * (1.f / 64.f) + 1e-6f) * 0.125f;   // fold attn scale
    float rk = rsqrtf(ssk * (1.f / 64.f) + 1e-6f);

    float2 gqv = *(const float2*)(gq + d0);
    float2 gkv = *(const float2*)(gk + d0);

    int o = ((b * HH + h) * TT + t) * DHH + d0;
    float2 qo = make_float2(qv.x * rq * gqv.x, qv.y * rq * gqv.y);
    float2 ko = make_float2(kv.x * rk * gkv.x, kv.y * rk * gkv.y);
    *(float2*)(g_q + o) = qo;
    *(float2*)(g_k + o) = ko;
    *(float2*)(g_v + o) = vv;
}

// =====================================================================
// Flash attention, fp32. grid = (T/64, B*H). 256 threads.
// 64 q-rows per block; stream over 34 kv tiles of 64.
// Soft bias: +1.0 where kv_frame > q_frame and both in video (uniform/tile pair).
// =====================================================================
#define SPAD 68
__global__ __launch_bounds__(256) void attn_kernel()
{
    extern __shared__ float sm[];
    float* Qs = sm;                   // [64][68]  Q^T (scaled)
    float* Ks = Qs + 64 * SPAD;       // [64][68]  K^T
    float* Vs = Ks + 64 * SPAD;       // [64][68]  V
    float* Ps = Vs + 64 * SPAD;       // [64][68]  P^T

    int qt = blockIdx.x;              // 0..33
    int bh = blockIdx.y;              // 0..31
    int tid = threadIdx.x;
    int tx = tid & 15, ty = tid >> 4;
    int ty4 = ty * 4, tx4 = tx * 4;

    const float* Qg = g_q + (bh * TT + qt * 64) * DHH;
    const float* Kg = g_k + bh * TT * DHH;
    const float* Vg = g_v + bh * TT * DHH;

    // Load Q tile transposed
#pragma unroll
    for (int it = 0; it < 4; it++) {
        int idx = tid + it * 256;
        int r = idx >> 4;
        int dq = (idx & 15) * 4;
        float4 v = *(const float4*)(Qg + r * DHH + dq);
        Qs[(dq + 0) * SPAD + r] = v.x;
        Qs[(dq + 1) * SPAD + r] = v.y;
        Qs[(dq + 2) * SPAD + r] = v.z;
        Qs[(dq + 3) * SPAD + r] = v.w;
    }

    float O[4][4];
    float m_r[4], l_r[4];
#pragma unroll
    for (int i = 0; i < 4; i++) {
        m_r[i] = -1e30f; l_r[i] = 0.f;
#pragma unroll
        for (int j = 0; j < 4; j++) O[i][j] = 0.f;
    }

    for (int kt = 0; kt < NKT; kt++) {
        __syncthreads();   // previous PV done with Vs/Ps; Q store visible on first iter
        // Load K (transposed) and V
        const float* Kt = Kg + kt * 64 * DHH;
        const float* Vt = Vg + kt * 64 * DHH;
#pragma unroll
        for (int it = 0; it < 4; it++) {
            int idx = tid + it * 256;
            int r = idx >> 4;
            int dq = (idx & 15) * 4;
            float4 kv4 = *(const float4*)(Kt + r * DHH + dq);
            Ks[(dq + 0) * SPAD + r] = kv4.x;
            Ks[(dq + 1) * SPAD + r] = kv4.y;
            Ks[(dq + 2) * SPAD + r] = kv4.z;
            Ks[(dq + 3) * SPAD + r] = kv4.w;
            float4 vv4 = *(const float4*)(Vt + r * DHH + dq);
            *(float4*)(Vs + r * SPAD + dq) = vv4;
        }
        __syncthreads();

        // S = Q^T-tile . K^T-tile  (each thread 4x4)
        float S[4][4];
#pragma unroll
        for (int i = 0; i < 4; i++)
#pragma unroll
            for (int j = 0; j < 4; j++) S[i][j] = 0.f;
#pragma unroll 16
        for (int d = 0; d < 64; d++) {
            float4 a = *(const float4*)(Qs + d * SPAD + ty4);
            float4 b = *(const float4*)(Ks + d * SPAD + tx4);
            float ar[4] = {a.x, a.y, a.z, a.w};
            float br[4] = {b.x, b.y, b.z, b.w};
#pragma unroll
            for (int i = 0; i < 4; i++)
#pragma unroll
                for (int j = 0; j < 4; j++) S[i][j] += ar[i] * br[j];
        }

        float biasv = (qt < NVTILES && kt < NVTILES && (kt >> 2) > (qt >> 2)) ? 1.0f : 0.0f;

        // Online softmax (rows replicated across 16 lanes sharing ty)
#pragma unroll
        for (int i = 0; i < 4; i++) {
            float s0 = S[i][0] + biasv, s1 = S[i][1] + biasv;
            float s2 = S[i][2] + biasv, s3 = S[i][3] + biasv;
            float mx = fmaxf(fmaxf(s0, s1), fmaxf(s2, s3));
#pragma unroll
            for (int off = 8; off > 0; off >>= 1)
                mx = fmaxf(mx, __shfl_xor_sync(0xffffffffu, mx, off));
            float mn = fmaxf(m_r[i], mx);
            float p0 = __expf(s0 - mn), p1 = __expf(s1 - mn);
            float p2 = __expf(s2 - mn), p3 = __expf(s3 - mn);
            float rs = p0 + p1 + p2 + p3;
#pragma unroll
            for (int off = 8; off > 0; off >>= 1)
                rs += __shfl_xor_sync(0xffffffffu, rs, off);
            float alpha = __expf(m_r[i] - mn);
            l_r[i] = l_r[i] * alpha + rs;
            m_r[i] = mn;
#pragma unroll
            for (int j = 0; j < 4; j++) O[i][j] *= alpha;
            // store P transposed: Ps[kv][m]
            Ps[(tx4 + 0) * SPAD + ty4 + i] = p0;
            Ps[(tx4 + 1) * SPAD + ty4 + i] = p1;
            Ps[(tx4 + 2) * SPAD + ty4 + i] = p2;
            Ps[(tx4 + 3) * SPAD + ty4 + i] = p3;
        }
        __syncthreads();

        // O += P . V
#pragma unroll 16
        for (int kc = 0; kc < 64; kc++) {
            float4 a = *(const float4*)(Ps + kc * SPAD + ty4);
            float4 b = *(const float4*)(Vs + kc * SPAD + tx4);
            float ar[4] = {a.x, a.y, a.z, a.w};
            float br[4] = {b.x, b.y, b.z, b.w};
#pragma unroll
            for (int i = 0; i < 4; i++)
#pragma unroll
                for (int j = 0; j < 4; j++) O[i][j] += ar[i] * br[j];
        }
    }

    // Write out: g_x[b][t][h*64 + d]
    int b = bh / HH, h = bh % HH;
#pragma unroll
    for (int i = 0; i < 4; i++) {
        int t = qt * 64 + ty4 + i;
        float inv = 1.f / l_r[i];
        float4 o = make_float4(O[i][0] * inv, O[i][1] * inv, O[i][2] * inv, O[i][3] * inv);
        *(float4*)(g_x + (b * TT + t) * DD + h * DHH + tx4) = o;
    }
}

// =====================================================================
// Launch
// =====================================================================
extern "C" void kernel_launch(void* const* d_in, const int* in_sizes, int n_in,
                              void* d_out, int out_size)
{
    const float* x1    = (const float*)d_in[0];
    const float* x2    = (const float*)d_in[1];
    const float* Wqkv1 = (const float*)d_in[2];
    const float* bqkv1 = (const float*)d_in[3];
    const float* Wqkv2 = (const float*)d_in[4];
    const float* bqkv2 = (const float*)d_in[5];
    const float* Wout1 = (const float*)d_in[6];
    const float* bout1 = (const float*)d_in[7];
    const float* Wout2 = (const float*)d_in[8];
    const float* bout2 = (const float*)d_in[9];
    const float* gq1   = (const float*)d_in[10];
    const float* gk1   = (const float*)d_in[11];
    const float* gq2   = (const float*)d_in[12];
    const float* gk2   = (const float*)d_in[13];
    float* out = (float*)d_out;

    float* p_qkv = nullptr; float* p_x = nullptr;
    cudaGetSymbolAddress((void**)&p_qkv, g_qkv);
    cudaGetSymbolAddress((void**)&p_x, g_x);

    // QKV projections: scatter rows into [B, T, 3D]
    sgemm_kernel<<<dim3(ND3 / 128, (BB * N1L) / 128), 256>>>(
        x1, Wqkv1, bqkv1, p_qkv, BB * N1L, ND3, DD,
        BB * N1L, 0, BB * N1L,          // A identity
        N1L, 0, TT);                    // C rows: b*T + n
    sgemm_kernel<<<dim3(ND3 / 128, (BB * N2L) / 128), 256>>>(
        x2, Wqkv2, bqkv2, p_qkv, BB * N2L, ND3, DD,
        BB * N2L, 0, BB * N2L,
        N2L, N1L, TT);                  // C rows: b*T + 2048 + n

    // RMSNorm + scatter to [B,H,T,64]
    rms_scatter_kernel<<<(BB * TT * HH * 32) / 256, 256>>>(gq1, gk1, gq2, gk2);

    // Attention
    int smem = 4 * 64 * SPAD * (int)sizeof(float);   // 69632 B
    cudaFuncSetAttribute(attn_kernel, cudaFuncAttributeMaxDynamicSharedMemorySize, smem);
    attn_kernel<<<dim3(NKT, BB * HH), 256, smem>>>();

    // Output projections
    sgemm_kernel<<<dim3(DD / 128, (BB * N1L) / 128), 256>>>(
        p_x, Wout1, bout1, out, BB * N1L, DD, DD,
        N1L, 0, TT,                     // A rows: b*T + n
        BB * N1L, 0, BB * N1L);         // C identity (out1 region)
    sgemm_kernel<<<dim3(DD / 128, (BB * N2L) / 128), 256>>>(
        p_x, Wout2, bout2, out + BB * N1L * DD, BB * N2L, DD, DD,
        N2L, N1L, TT,                   // A rows: b*T + 2048 + n
        BB * N2L, 0, BB * N2L);         // C identity (out2 region)
}

// round 2
// speedup vs baseline: 2.7176x; 2.7176x over previous
#include <cuda_runtime.h>
#include <math.h>
#include <stdint.h>

// ---------------- problem constants ----------------
#define BB   2
#define N1L  2048
#define N2L  128
#define TT   2176          // N1 + N2
#define DD   1024
#define HH   16
#define DHH  64
#define ND3  3072          // 3*D
#define NKT  34            // T/64 kv tiles
#define QTR  128           // q rows per attn block
#define NQT  17            // T/128 q tiles

// ---------------- scratch (__device__ globals; no allocs allowed) ----------------
__device__ float g_qkv[BB * TT * ND3];        // [B, T, 3*D]
__device__ float g_q[BB * HH * TT * DHH];     // [B,H,T,64]  (1/8 scale folded)
__device__ float g_k[BB * HH * TT * DHH];
__device__ float g_v[BB * HH * TT * DHH];
__device__ float g_x[BB * TT * DD];           // attention output, heads merged

// ---------------- helpers ----------------
__device__ __forceinline__ float to_tf32(float x) {
    uint32_t u;
    asm("cvt.rna.tf32.f32 %0, %1;" : "=r"(u) : "f"(x));
    return __uint_as_float(u);
}

__device__ __forceinline__ void mma_tf32(float* c, const float* a, const float* b) {
    asm volatile(
        "mma.sync.aligned.m16n8k8.row.col.f32.tf32.tf32.f32 "
        "{%0,%1,%2,%3}, {%4,%5,%6,%7}, {%8,%9}, {%0,%1,%2,%3};"
        : "+f"(c[0]), "+f"(c[1]), "+f"(c[2]), "+f"(c[3])
        : "r"(__float_as_uint(a[0])), "r"(__float_as_uint(a[1])),
          "r"(__float_as_uint(a[2])), "r"(__float_as_uint(a[3])),
          "r"(__float_as_uint(b[0])), "r"(__float_as_uint(b[1])));
}

// =====================================================================
// tf32 tensor-core SGEMM: C[remap_c(r)] = A[remap_a(r)] @ W + bias
// BM=128, BN=128, BK=16; 256 threads = 8 warps of 64x32 warp-tiles.
// =====================================================================
#define ALD 20     // As row stride (conflict-free for frag loads)
#define BLD 136    // Bs row stride
__global__ __launch_bounds__(256) void sgemm_tf32(
    const float* __restrict__ A, const float* __restrict__ W,
    const float* __restrict__ bias, float* __restrict__ C,
    int M, int N, int K,
    int a_per, int a_base, int a_span,
    int c_per, int c_base, int c_span)
{
    __shared__ float As[128 * ALD];
    __shared__ float Bs[16 * BLD];

    int tid = threadIdx.x;
    int bm = blockIdx.y, bn = blockIdx.x;
    int warp = tid >> 5, lane = tid & 31;
    int g = lane >> 2, tig = lane & 3;
    int wm = (warp >> 2) * 64, wn = (warp & 3) * 32;

    // A global: 2 float4 / thread
    int a_row[2], a_kq[2];
    const float* a_ptr[2];
#pragma unroll
    for (int i = 0; i < 2; i++) {
        int idx = tid + i * 256;
        a_row[i] = idx >> 2;
        a_kq[i]  = (idx & 3) * 4;
        int gr = bm * 128 + a_row[i];
        int arow = (gr / a_per) * a_span + a_base + (gr % a_per);
        a_ptr[i] = A + (size_t)arow * K + a_kq[i];
    }
    // B global: 2 float4 / thread
    int b_kr[2], b_nq[2];
    const float* b_ptr[2];
#pragma unroll
    for (int i = 0; i < 2; i++) {
        int idx = tid + i * 256;
        b_kr[i] = idx >> 5;
        b_nq[i] = (idx & 31) * 4;
        b_ptr[i] = W + (size_t)b_kr[i] * N + bn * 128 + b_nq[i];
    }

    float acc[4][4][4];
#pragma unroll
    for (int mt = 0; mt < 4; mt++)
#pragma unroll
        for (int nt = 0; nt < 4; nt++)
#pragma unroll
            for (int r = 0; r < 4; r++) acc[mt][nt][r] = 0.f;

    for (int kk = 0; kk < K; kk += 16) {
        float4 av[2], bv[2];
#pragma unroll
        for (int i = 0; i < 2; i++) {
            av[i] = *(const float4*)(a_ptr[i] + kk);
            bv[i] = *(const float4*)(b_ptr[i] + (size_t)kk * N);
        }
        __syncthreads();
#pragma unroll
        for (int i = 0; i < 2; i++) {
            float* as = &As[a_row[i] * ALD + a_kq[i]];
            as[0] = to_tf32(av[i].x); as[1] = to_tf32(av[i].y);
            as[2] = to_tf32(av[i].z); as[3] = to_tf32(av[i].w);
            float* bs = &Bs[b_kr[i] * BLD + b_nq[i]];
            bs[0] = to_tf32(bv[i].x); bs[1] = to_tf32(bv[i].y);
            bs[2] = to_tf32(bv[i].z); bs[3] = to_tf32(bv[i].w);
        }
        __syncthreads();

#pragma unroll
        for (int ks = 0; ks < 16; ks += 8) {
            float afr[4][4], bfr[4][2];
#pragma unroll
            for (int mt = 0; mt < 4; mt++) {
                int rb = wm + mt * 16;
                afr[mt][0] = As[(rb + g)     * ALD + ks + tig];
                afr[mt][1] = As[(rb + g + 8) * ALD + ks + tig];
                afr[mt][2] = As[(rb + g)     * ALD + ks + tig + 4];
                afr[mt][3] = As[(rb + g + 8) * ALD + ks + tig + 4];
            }
#pragma unroll
            for (int nt = 0; nt < 4; nt++) {
                int nb = wn + nt * 8;
                bfr[nt][0] = Bs[(ks + tig)     * BLD + nb + g];
                bfr[nt][1] = Bs[(ks + tig + 4) * BLD + nb + g];
            }
#pragma unroll
            for (int mt = 0; mt < 4; mt++)
#pragma unroll
                for (int nt = 0; nt < 4; nt++)
                    mma_tf32(acc[mt][nt], afr[mt], bfr[nt]);
        }
    }

    // Epilogue
#pragma unroll
    for (int mt = 0; mt < 4; mt++) {
        int gm0 = bm * 128 + wm + mt * 16 + g;
        int gm1 = gm0 + 8;
        int cr0 = (gm0 / c_per) * c_span + c_base + (gm0 % c_per);
        int cr1 = (gm1 / c_per) * c_span + c_base + (gm1 % c_per);
#pragma unroll
        for (int nt = 0; nt < 4; nt++) {
            int cn = bn * 128 + wn + nt * 8 + 2 * tig;
            float2 bi = *(const float2*)(bias + cn);
            float2 o0 = make_float2(acc[mt][nt][0] + bi.x, acc[mt][nt][1] + bi.y);
            float2 o1 = make_float2(acc[mt][nt][2] + bi.x, acc[mt][nt][3] + bi.y);
            *(float2*)(C + (size_t)cr0 * N + cn) = o0;
            *(float2*)(C + (size_t)cr1 * N + cn) = o1;
        }
    }
}

// =====================================================================
// RMSNorm(q,k) + scatter q/k/v from [B,T,3D] into [B,H,T,64].
// =====================================================================
__global__ __launch_bounds__(256) void rms_scatter_kernel(
    const float* __restrict__ gq1, const float* __restrict__ gk1,
    const float* __restrict__ gq2, const float* __restrict__ gk2)
{
    int warp = (blockIdx.x * blockDim.x + threadIdx.x) >> 5;
    int lane = threadIdx.x & 31;
    if (warp >= BB * TT * HH) return;
    int h = warp % HH;
    int bt = warp / HH;
    int t = bt % TT;
    int b = bt / TT;

    const float* base = g_qkv + (size_t)(b * TT + t) * ND3;
    const float* gq = (t < N1L) ? gq1 : gq2;
    const float* gk = (t < N1L) ? gk1 : gk2;

    int d0 = lane * 2;
    float2 qv = *(const float2*)(base + h * DHH + d0);
    float2 kv = *(const float2*)(base + DD + h * DHH + d0);
    float2 vv = *(const float2*)(base + 2 * DD + h * DHH + d0);

    float ssq = qv.x * qv.x + qv.y * qv.y;
    float ssk = kv.x * kv.x + kv.y * kv.y;
#pragma unroll
    for (int off = 16; off > 0; off >>= 1) {
        ssq += __shfl_xor_sync(0xffffffffu, ssq, off);
        ssk += __shfl_xor_sync(0xffffffffu, ssk, off);
    }
    float rq = rsqrtf(ssq * (1.f / 64.f) + 1e-6f) * 0.125f;
    float rk = rsqrtf(ssk * (1.f / 64.f) + 1e-6f);

    float2 gqv = *(const float2*)(gq + d0);
    float2 gkv = *(const float2*)(gk + d0);

    int o = ((b * HH + h) * TT + t) * DHH + d0;
    *(float2*)(g_q + o) = make_float2(qv.x * rq * gqv.x, qv.y * rq * gqv.y);
    *(float2*)(g_k + o) = make_float2(kv.x * rk * gkv.x, kv.y * rk * gkv.y);
    *(float2*)(g_v + o) = vv;
}

// =====================================================================
// Flash attention with tf32 mma. grid = (17, B*H). 256 threads (8 warps).
// 128 q-rows/block (warp w owns rows w*16..w*16+15), 64-kv tiles.
// Soft bias +1.0 where kv_frame > q_frame, both in video (uniform per tile).
// =====================================================================
#define QLD 68     // Qs/Ps row stride
#define KLD 72     // Ks/Vs row stride
__global__ __launch_bounds__(256) void attn_kernel()
{
    extern __shared__ float sm[];
    float* Qs = sm;                     // [128][68]  (q, d)
    float* Ps = Qs + QTR * QLD;         // [128][68]  (q, kv)
    float* Ks = Ps + QTR * QLD;         // [64][72]   (d, kv)  transposed
    float* Vs = Ks + 64 * KLD;          // [64][72]   (kv, d)

    int qt = blockIdx.x;                // 0..16
    int bh = blockIdx.y;                // 0..31
    int tid = threadIdx.x;
    int warp = tid >> 5, lane = tid & 31;
    int g = lane >> 2, tig = lane & 3;
    int mb = warp * 16;

    const float* Qg = g_q + (size_t)(bh * TT + qt * QTR) * DHH;
    const float* Kg = g_k + (size_t)bh * TT * DHH;
    const float* Vg = g_v + (size_t)bh * TT * DHH;

    // Load Q tile (tf32-rounded): 128x64 floats = 2048 float4
#pragma unroll
    for (int i = 0; i < 8; i++) {
        int idx = tid + i * 256;
        int r = idx >> 4, dq = (idx & 15) * 4;
        float4 v = *(const float4*)(Qg + r * DHH + dq);
        float* qs = &Qs[r * QLD + dq];
        qs[0] = to_tf32(v.x); qs[1] = to_tf32(v.y);
        qs[2] = to_tf32(v.z); qs[3] = to_tf32(v.w);
    }

    float O[8][4];
    float m_r[2], l_r[2];
#pragma unroll
    for (int nt = 0; nt < 8; nt++)
#pragma unroll
        for (int r = 0; r < 4; r++) O[nt][r] = 0.f;
    m_r[0] = m_r[1] = -1e30f;
    l_r[0] = l_r[1] = 0.f;

    for (int kt = 0; kt < NKT; kt++) {
        __syncthreads();   // prev PV done with Ks/Vs; Q visible on iter 0
        const float* Kt = Kg + kt * 64 * DHH;
        const float* Vt = Vg + kt * 64 * DHH;
#pragma unroll
        for (int i = 0; i < 4; i++) {
            int idx = tid + i * 256;
            int r = idx >> 4, dq = (idx & 15) * 4;
            float4 kv4 = *(const float4*)(Kt + r * DHH + dq);
            Ks[(dq + 0) * KLD + r] = to_tf32(kv4.x);
            Ks[(dq + 1) * KLD + r] = to_tf32(kv4.y);
            Ks[(dq + 2) * KLD + r] = to_tf32(kv4.z);
            Ks[(dq + 3) * KLD + r] = to_tf32(kv4.w);
            float4 vv4 = *(const float4*)(Vt + r * DHH + dq);
            float* vs = &Vs[r * KLD + dq];
            vs[0] = to_tf32(vv4.x); vs[1] = to_tf32(vv4.y);
            vs[2] = to_tf32(vv4.z); vs[3] = to_tf32(vv4.w);
        }
        __syncthreads();

        // S = Q . K^T  (warp: m16 x n64, k=64)
        float S[8][4];
#pragma unroll
        for (int nt = 0; nt < 8; nt++)
#pragma unroll
            for (int r = 0; r < 4; r++) S[nt][r] = 0.f;
#pragma unroll
        for (int ks = 0; ks < 8; ks++) {
            int k0 = ks * 8;
            float a[4];
            a[0] = Qs[(mb + g)     * QLD + k0 + tig];
            a[1] = Qs[(mb + g + 8) * QLD + k0 + tig];
            a[2] = Qs[(mb + g)     * QLD + k0 + tig + 4];
            a[3] = Qs[(mb + g + 8) * QLD + k0 + tig + 4];
#pragma unroll
            for (int nt = 0; nt < 8; nt++) {
                float b[2];
                b[0] = Ks[(k0 + tig)     * KLD + nt * 8 + g];
                b[1] = Ks[(k0 + tig + 4) * KLD + nt * 8 + g];
                mma_tf32(S[nt], a, b);
            }
        }

        float biasv = (qt < 16 && kt < 32 && (kt >> 2) > (qt >> 1)) ? 1.0f : 0.0f;

        // Online softmax per row (rows: mb+g, mb+g+8); row spans lanes g*4..g*4+3
#pragma unroll
        for (int r = 0; r < 2; r++) {
            float mx = -1e30f;
#pragma unroll
            for (int nt = 0; nt < 8; nt++) {
                S[nt][2 * r]     += biasv;
                S[nt][2 * r + 1] += biasv;
                mx = fmaxf(mx, fmaxf(S[nt][2 * r], S[nt][2 * r + 1]));
            }
            mx = fmaxf(mx, __shfl_xor_sync(0xffffffffu, mx, 1));
            mx = fmaxf(mx, __shfl_xor_sync(0xffffffffu, mx, 2));
            float mn = fmaxf(m_r[r], mx);
            float rs = 0.f;
            int row = mb + g + 8 * r;
#pragma unroll
            for (int nt = 0; nt < 8; nt++) {
                float p0 = __expf(S[nt][2 * r]     - mn);
                float p1 = __expf(S[nt][2 * r + 1] - mn);
                rs += p0 + p1;
                Ps[row * QLD + nt * 8 + 2 * tig]     = to_tf32(p0);
                Ps[row * QLD + nt * 8 + 2 * tig + 1] = to_tf32(p1);
            }
            rs += __shfl_xor_sync(0xffffffffu, rs, 1);
            rs += __shfl_xor_sync(0xffffffffu, rs, 2);
            float alpha = __expf(m_r[r] - mn);
            l_r[r] = l_r[r] * alpha + rs;
            m_r[r] = mn;
#pragma unroll
            for (int nt = 0; nt < 8; nt++) {
                O[nt][2 * r]     *= alpha;
                O[nt][2 * r + 1] *= alpha;
            }
        }
        __syncwarp();   // Ps rows are warp-private; visibility only

        // O += P . V  (warp: m16 x n64, k=64)
#pragma unroll
        for (int ks = 0; ks < 8; ks++) {
            int k0 = ks * 8;
            float a[4];
            a[0] = Ps[(mb + g)     * QLD + k0 + tig];
            a[1] = Ps[(mb + g + 8) * QLD + k0 + tig];
            a[2] = Ps[(mb + g)     * QLD + k0 + tig + 4];
            a[3] = Ps[(mb + g + 8) * QLD + k0 + tig + 4];
#pragma unroll
            for (int nt = 0; nt < 8; nt++) {
                float b[2];
                b[0] = Vs[(k0 + tig)     * KLD + nt * 8 + g];
                b[1] = Vs[(k0 + tig + 4) * KLD + nt * 8 + g];
                mma_tf32(O[nt], a, b);
            }
        }
    }

    // Write out: g_x[b][t][h*64 + d]
    int b = bh / HH, h = bh % HH;
    float inv0 = 1.f / l_r[0], inv1 = 1.f / l_r[1];
    int t0 = qt * QTR + mb + g;
#pragma unroll
    for (int nt = 0; nt < 8; nt++) {
        int col = h * DHH + nt * 8 + 2 * tig;
        *(float2*)(g_x + (size_t)(b * TT + t0) * DD + col) =
            make_float2(O[nt][0] * inv0, O[nt][1] * inv0);
        *(float2*)(g_x + (size_t)(b * TT + t0 + 8) * DD + col) =
            make_float2(O[nt][2] * inv1, O[nt][3] * inv1);
    }
}

// =====================================================================
// Launch
// =====================================================================
extern "C" void kernel_launch(void* const* d_in, const int* in_sizes, int n_in,
                              void* d_out, int out_size)
{
    const float* x1    = (const float*)d_in[0];
    const float* x2    = (const float*)d_in[1];
    const float* Wqkv1 = (const float*)d_in[2];
    const float* bqkv1 = (const float*)d_in[3];
    const float* Wqkv2 = (const float*)d_in[4];
    const float* bqkv2 = (const float*)d_in[5];
    const float* Wout1 = (const float*)d_in[6];
    const float* bout1 = (const float*)d_in[7];
    const float* Wout2 = (const float*)d_in[8];
    const float* bout2 = (const float*)d_in[9];
    const float* gq1   = (const float*)d_in[10];
    const float* gk1   = (const float*)d_in[11];
    const float* gq2   = (const float*)d_in[12];
    const float* gk2   = (const float*)d_in[13];
    float* out = (float*)d_out;

    float* p_qkv = nullptr; float* p_x = nullptr;
    cudaGetSymbolAddress((void**)&p_qkv, g_qkv);
    cudaGetSymbolAddress((void**)&p_x, g_x);

    // QKV projections -> [B, T, 3D]
    sgemm_tf32<<<dim3(ND3 / 128, (BB * N1L) / 128), 256>>>(
        x1, Wqkv1, bqkv1, p_qkv, BB * N1L, ND3, DD,
        BB * N1L, 0, BB * N1L,
        N1L, 0, TT);
    sgemm_tf32<<<dim3(ND3 / 128, (BB * N2L) / 128), 256>>>(
        x2, Wqkv2, bqkv2, p_qkv, BB * N2L, ND3, DD,
        BB * N2L, 0, BB * N2L,
        N2L, N1L, TT);

    // RMSNorm + scatter to [B,H,T,64]
    rms_scatter_kernel<<<(BB * TT * HH * 32) / 256, 256>>>(gq1, gk1, gq2, gk2);

    // Attention
    int smem = (2 * QTR * QLD + 2 * 64 * KLD) * (int)sizeof(float);  // 106496
    cudaFuncSetAttribute(attn_kernel, cudaFuncAttributeMaxDynamicSharedMemorySize, smem);
    attn_kernel<<<dim3(NQT, BB * HH), 256, smem>>>();

    // Output projections
    sgemm_tf32<<<dim3(DD / 128, (BB * N1L) / 128), 256>>>(
        p_x, Wout1, bout1, out, BB * N1L, DD, DD,
        N1L, 0, TT,
        BB * N1L, 0, BB * N1L);
    sgemm_tf32<<<dim3(DD / 128, (BB * N2L) / 128), 256>>>(
        p_x, Wout2, bout2, out + (size_t)BB * N1L * DD, BB * N2L, DD, DD,
        N2L, N1L, TT,
        BB * N2L, 0, BB * N2L);
}